// round 14
// baseline (speedup 1.0000x reference)
#include <cuda_runtime.h>
#include <cuda_bf16.h>
#include <math.h>
#include <stdint.h>

// Problem constants
#define B 4
#define L 2048
#define S 2048
#define D 1024
#define H 16
#define DH 64

// ---------------------------------------------------------------------------
// Scratch (device globals — no allocation allowed)
// ---------------------------------------------------------------------------
__device__ __nv_bfloat16 g_ain_hi[B * L * D];
__device__ __nv_bfloat16 g_ain_lo[B * L * D];
__device__ __nv_bfloat16 g_bin_hi[B * L * D];
__device__ __nv_bfloat16 g_bin_lo[B * L * D];
__device__ __nv_bfloat16 g_cin_hi[B * L * D];
__device__ __nv_bfloat16 g_cin_lo[B * L * D];
__device__ __nv_bfloat16 g_wq_hi[D * D];
__device__ __nv_bfloat16 g_wq_lo[D * D];
__device__ __nv_bfloat16 g_wk_hi[D * D];
__device__ __nv_bfloat16 g_wk_lo[D * D];
__device__ __nv_bfloat16 g_wv_hi[D * D];
__device__ __nv_bfloat16 g_wv_lo[D * D];
__device__ __nv_bfloat16 g_wo_hi[D * D];
__device__ __nv_bfloat16 g_wo_lo[D * D];
__device__ __nv_bfloat16 g_q_hi[B * L * D];
__device__ __nv_bfloat16 g_q_lo[B * L * D];
__device__ __nv_bfloat16 g_k_hi[B * S * D];
__device__ __nv_bfloat16 g_k_lo[B * S * D];
__device__ __nv_bfloat16 g_v_hi[B * S * D];
__device__ __nv_bfloat16 g_v_lo[B * S * D];
__device__ __nv_bfloat16 g_o_hi[B * L * D];
__device__ __nv_bfloat16 g_o_lo[B * L * D];

// ---------------------------------------------------------------------------
// Helpers (baseline compute_103-safe PTX only)
// ---------------------------------------------------------------------------
__device__ __forceinline__ uint32_t smem_u32(const void* p) {
    uint32_t a;
    asm("{ .reg .u64 t; cvta.to.shared.u64 t, %1; cvt.u32.u64 %0, t; }"
        : "=r"(a) : "l"(p));
    return a;
}

#define CP16(dst, src) \
    asm volatile("cp.async.cg.shared.global [%0], [%1], 16;" \
        :: "r"(dst), "l"(src) : "memory")

#define CP_COMMIT() asm volatile("cp.async.commit_group;" ::: "memory")
#define CP_WAIT1()  asm volatile("cp.async.wait_group 1;" ::: "memory")

#define LDSM_X4(r0, r1, r2, r3, addr) \
    asm volatile("ldmatrix.sync.aligned.m8n8.x4.shared.b16 {%0,%1,%2,%3}, [%4];" \
        : "=r"(r0), "=r"(r1), "=r"(r2), "=r"(r3) : "r"(addr))

#define LDSM_X4_T(r0, r1, r2, r3, addr) \
    asm volatile("ldmatrix.sync.aligned.m8n8.x4.trans.shared.b16 {%0,%1,%2,%3}, [%4];" \
        : "=r"(r0), "=r"(r1), "=r"(r2), "=r"(r3) : "r"(addr))

#define MMA_BF16(c, a, b0, b1) \
    asm volatile("mma.sync.aligned.m16n8k16.row.col.f32.bf16.bf16.f32 " \
        "{%0,%1,%2,%3}, {%4,%5,%6,%7}, {%8,%9}, {%0,%1,%2,%3};" \
        : "+f"((c)[0]), "+f"((c)[1]), "+f"((c)[2]), "+f"((c)[3]) \
        : "r"((a)[0]), "r"((a)[1]), "r"((a)[2]), "r"((a)[3]), \
          "r"(b0), "r"(b1))

__device__ __forceinline__ float ex2f(float x) {
    float r;
    asm("ex2.approx.f32 %0, %1;" : "=f"(r) : "f"(x));
    return r;
}

__device__ __forceinline__ uint32_t pack_bf16x2(float lo, float hi) {
    uint32_t r;
    asm("cvt.rn.bf16x2.f32 %0, %1, %2;" : "=r"(r) : "f"(hi), "f"(lo));
    return r;
}

__device__ __forceinline__ void split_pack(float v0, float v1,
                                           uint32_t& hp, uint32_t& lp) {
    __nv_bfloat16 h0 = __float2bfloat16(v0);
    __nv_bfloat16 h1 = __float2bfloat16(v1);
    __nv_bfloat162 hh(h0, h1);
    hp = *reinterpret_cast<uint32_t*>(&hh);
    lp = pack_bf16x2(v0 - __bfloat162float(h0), v1 - __bfloat162float(h1));
}

// ---------------------------------------------------------------------------
// Split kernels (merged: weights x4, inputs x3)
// ---------------------------------------------------------------------------
__device__ __forceinline__ void split_body(const float* __restrict__ x,
                                           __nv_bfloat16* __restrict__ hi,
                                           __nv_bfloat16* __restrict__ lo, int n4)
{
    int i = blockIdx.x * blockDim.x + threadIdx.x;
    if (i >= n4) return;
    float4 v = reinterpret_cast<const float4*>(x)[i];
    uint2 hv, lv;
    split_pack(v.x, v.y, hv.x, lv.x);
    split_pack(v.z, v.w, hv.y, lv.y);
    reinterpret_cast<uint2*>(hi)[i] = hv;
    reinterpret_cast<uint2*>(lo)[i] = lv;
}

__global__ __launch_bounds__(256)
void split_w4_kernel(const float* __restrict__ Wq, const float* __restrict__ Wk,
                     const float* __restrict__ Wv, const float* __restrict__ Wo)
{
    const int seg = blockIdx.y;
    const float* src = (seg == 0) ? Wq : (seg == 1) ? Wk : (seg == 2) ? Wv : Wo;
    __nv_bfloat16* hi = (seg == 0) ? g_wq_hi : (seg == 1) ? g_wk_hi
                       : (seg == 2) ? g_wv_hi : g_wo_hi;
    __nv_bfloat16* lo = (seg == 0) ? g_wq_lo : (seg == 1) ? g_wk_lo
                       : (seg == 2) ? g_wv_lo : g_wo_lo;
    split_body(src, hi, lo, D * D / 4);
}

__global__ __launch_bounds__(256)
void split_in3_kernel(const float* __restrict__ q, const float* __restrict__ k,
                      const float* __restrict__ v)
{
    const int seg = blockIdx.y;
    const float* src = (seg == 0) ? q : (seg == 1) ? k : v;
    __nv_bfloat16* hi = (seg == 0) ? g_ain_hi : (seg == 1) ? g_bin_hi : g_cin_hi;
    __nv_bfloat16* lo = (seg == 0) ? g_ain_lo : (seg == 1) ? g_bin_lo : g_cin_lo;
    split_body(src, hi, lo, B * L * D / 4);
}

// ---------------------------------------------------------------------------
// HMMA split-bf16 GEMM body:  Y[m, n] = sum_k A[m,k] * W[n,k]
// CTA tile 128x128, warp tile 64x32 (8 warps as 2x4), k-chunk 32.
// 2-stage double buffer (80 KB smem) + <=128 regs -> 2 CTAs/SM.
// ---------------------------------------------------------------------------
#define KDIM 1024
#define NCH 32
#define PITCH 80
#define TSZ (128 * PITCH)        // 10240
#define STAGE_B (4 * TSZ)        // 40960
#define GEMM_SMEM (2 * STAGE_B)  // 81920

#define QSCALE (0.125f * 1.4426950408889634f)

template<bool BF16OUT>
__device__ __forceinline__ void gemm_body(
    const __nv_bfloat16* __restrict__ Ahi, const __nv_bfloat16* __restrict__ Alo,
    const __nv_bfloat16* __restrict__ Whi, const __nv_bfloat16* __restrict__ Wlo,
    float* __restrict__ Yf, __nv_bfloat16* __restrict__ Yhi,
    __nv_bfloat16* __restrict__ Ylo, float scale)
{
    extern __shared__ char smem[];
    const uint32_t sb = smem_u32(smem);
    const int tid = threadIdx.x;
    const int lane = tid & 31;
    const int wid = tid >> 5;
    const int warp_m = wid >> 2;
    const int warp_n = wid & 3;
    const int m0 = blockIdx.y * 128;
    const int n0 = blockIdx.x * 128;

    float acc[4][4][4];
#pragma unroll
    for (int a = 0; a < 4; a++)
#pragma unroll
        for (int b = 0; b < 4; b++)
#pragma unroll
            for (int c = 0; c < 4; c++) acc[a][b][c] = 0.f;

    auto prefetch = [&](int c, int stage) {
        const uint32_t sbase = sb + stage * STAGE_B;
        const int k0 = c * 32;
#pragma unroll
        for (int j = 0; j < 2; j++) {
            const int idx = j * 256 + tid;
            const int r  = (idx & 7) + (idx >> 5) * 8;
            const int ch = (idx >> 3) & 3;
            const uint32_t so = (uint32_t)(r * PITCH + ch * 16);
            const __nv_bfloat16* ga_hi = Ahi + (size_t)(m0 + r) * KDIM + k0 + ch * 8;
            const __nv_bfloat16* ga_lo = Alo + (size_t)(m0 + r) * KDIM + k0 + ch * 8;
            const __nv_bfloat16* gb_hi = Whi + (size_t)(n0 + r) * KDIM + k0 + ch * 8;
            const __nv_bfloat16* gb_lo = Wlo + (size_t)(n0 + r) * KDIM + k0 + ch * 8;
            CP16(sbase + so,           ga_hi);
            CP16(sbase + TSZ + so,     ga_lo);
            CP16(sbase + 2 * TSZ + so, gb_hi);
            CP16(sbase + 3 * TSZ + so, gb_lo);
        }
    };

    prefetch(0, 0); CP_COMMIT();
    prefetch(1, 1); CP_COMMIT();

    const int lr = lane & 15;
    const int lh = lane >> 4;
    const int br = (lane & 7) + ((lane >> 4) & 1) * 8;
    const int bk = ((lane >> 3) & 1) * 16;

    for (int c = 0; c < NCH; c++) {
        const int stage = c & 1;
        CP_WAIT1();
        __syncthreads();
        const uint32_t sbase = sb + stage * STAGE_B;

#pragma unroll
        for (int s = 0; s < 2; s++) {
            uint32_t ah[4][4], al[4][4];
#pragma unroll
            for (int mt = 0; mt < 4; mt++) {
                const uint32_t ad = sbase +
                    (uint32_t)((warp_m * 64 + mt * 16 + lr) * PITCH + s * 32 + lh * 16);
                LDSM_X4(ah[mt][0], ah[mt][1], ah[mt][2], ah[mt][3], ad);
                LDSM_X4(al[mt][0], al[mt][1], al[mt][2], al[mt][3], ad + TSZ);
            }
#pragma unroll
            for (int np = 0; np < 2; np++) {
                const uint32_t bd = sbase + 2 * TSZ +
                    (uint32_t)((warp_n * 32 + np * 16 + br) * PITCH + s * 32 + bk);
                uint32_t t0, t1, t2, t3, u0, u1, u2, u3;
                LDSM_X4(t0, t1, t2, t3, bd);
                LDSM_X4(u0, u1, u2, u3, bd + TSZ);
#pragma unroll
                for (int mt = 0; mt < 4; mt++) {
                    MMA_BF16(acc[mt][np * 2], ah[mt], t0, t1);
                    MMA_BF16(acc[mt][np * 2], ah[mt], u0, u1);
                    MMA_BF16(acc[mt][np * 2], al[mt], t0, t1);
                    MMA_BF16(acc[mt][np * 2 + 1], ah[mt], t2, t3);
                    MMA_BF16(acc[mt][np * 2 + 1], ah[mt], u2, u3);
                    MMA_BF16(acc[mt][np * 2 + 1], al[mt], t2, t3);
                }
            }
        }
        __syncthreads();   // compute done before overwriting this stage
        if (c + 2 < NCH) prefetch(c + 2, stage);
        CP_COMMIT();
    }

    const int gr = lane >> 2;
    const int gc = (lane & 3) * 2;
    const int row0 = m0 + warp_m * 64;
    const int col0 = n0 + warp_n * 32;
#pragma unroll
    for (int mt = 0; mt < 4; mt++) {
#pragma unroll
        for (int nt = 0; nt < 4; nt++) {
            const int r0 = row0 + mt * 16 + gr;
            const int cc = col0 + nt * 8 + gc;
            if (BF16OUT) {
                uint32_t hp, lp;
                split_pack(acc[mt][nt][0] * scale, acc[mt][nt][1] * scale, hp, lp);
                *reinterpret_cast<uint32_t*>(Yhi + (size_t)r0 * KDIM + cc) = hp;
                *reinterpret_cast<uint32_t*>(Ylo + (size_t)r0 * KDIM + cc) = lp;
                split_pack(acc[mt][nt][2] * scale, acc[mt][nt][3] * scale, hp, lp);
                *reinterpret_cast<uint32_t*>(Yhi + (size_t)(r0 + 8) * KDIM + cc) = hp;
                *reinterpret_cast<uint32_t*>(Ylo + (size_t)(r0 + 8) * KDIM + cc) = lp;
            } else {
                float* p0 = Yf + (size_t)r0 * KDIM + cc;
                float* p1 = p0 + 8 * KDIM;
                asm volatile("st.global.v2.f32 [%0], {%1, %2};"
                    :: "l"(p0), "f"(acc[mt][nt][0]), "f"(acc[mt][nt][1]) : "memory");
                asm volatile("st.global.v2.f32 [%0], {%1, %2};"
                    :: "l"(p1), "f"(acc[mt][nt][2]), "f"(acc[mt][nt][3]) : "memory");
            }
        }
    }
}

// Merged Q/K/V projections: blockIdx.z selects operand set (all device symbols).
__global__ __launch_bounds__(256, 2)
void gemm_qkv_kernel()
{
    const int z = blockIdx.z;
    const __nv_bfloat16* Ahi = (z == 0) ? g_ain_hi : (z == 1) ? g_bin_hi : g_cin_hi;
    const __nv_bfloat16* Alo = (z == 0) ? g_ain_lo : (z == 1) ? g_bin_lo : g_cin_lo;
    const __nv_bfloat16* Whi = (z == 0) ? g_wq_hi : (z == 1) ? g_wk_hi : g_wv_hi;
    const __nv_bfloat16* Wlo = (z == 0) ? g_wq_lo : (z == 1) ? g_wk_lo : g_wv_lo;
    __nv_bfloat16* Yhi = (z == 0) ? g_q_hi : (z == 1) ? g_k_hi : g_v_hi;
    __nv_bfloat16* Ylo = (z == 0) ? g_q_lo : (z == 1) ? g_k_lo : g_v_lo;
    const float sc = (z == 0) ? QSCALE : 1.f;
    gemm_body<true>(Ahi, Alo, Whi, Wlo, nullptr, Yhi, Ylo, sc);
}

// Output projection: fp32 result into harness buffer.
__global__ __launch_bounds__(256, 2)
void gemm_o_kernel(float* __restrict__ out)
{
    gemm_body<false>(g_o_hi, g_o_lo, g_wo_hi, g_wo_lo, out, nullptr, nullptr, 1.f);
}

// ---------------------------------------------------------------------------
// HMMA flash attention (causal), split-bf16, log2-domain softmax. (unchanged)
// CTA: 128 q-rows (8 warps x 16), kv-tiles of 64, dh=64.
// ---------------------------------------------------------------------------
#define APITCH 144
#define AQT (128 * APITCH)
#define AKT (64 * APITCH)
#define ASTG (4 * AKT)
#define ATTN_SMEM (2 * AQT + 3 * ASTG)   // 147456

__global__ __launch_bounds__(256, 1)
void attn_mma_kernel(const __nv_bfloat16* __restrict__ Qhi,
                     const __nv_bfloat16* __restrict__ Qlo,
                     const __nv_bfloat16* __restrict__ Khi,
                     const __nv_bfloat16* __restrict__ Klo,
                     const __nv_bfloat16* __restrict__ Vhi,
                     const __nv_bfloat16* __restrict__ Vlo,
                     __nv_bfloat16* __restrict__ Ohi,
                     __nv_bfloat16* __restrict__ Olo)
{
    extern __shared__ char smem[];
    const uint32_t sb = smem_u32(smem);
    const int tid = threadIdx.x;
    const int lane = tid & 31;
    const int wid = tid >> 5;
    const int mq = (L / 128 - 1) - blockIdx.x;
    const int bh = blockIdx.y;
    const int b = bh >> 4;
    const int h = bh & 15;
    const int m0 = mq * 128;
    const int ntiles = mq * 2 + 2;

    const size_t qg = ((size_t)b * L + m0) * D + h * DH;
    const size_t kg = (size_t)b * S * D + h * DH;

#pragma unroll
    for (int i = 0; i < 8; i++) {
        const int idx = i * 256 + tid;
        const int tsr = idx >> 10;
        const int rem = idx & 1023;
        const int row = rem >> 3;
        const int ch = rem & 7;
        const __nv_bfloat16* src = (tsr ? Qlo : Qhi) + qg + (size_t)row * D + ch * 8;
        CP16(sb + tsr * AQT + row * APITCH + ch * 16, src);
    }

    auto prefetch_kv = [&](int j, int stage) {
        const int n0 = j * 64;
#pragma unroll
        for (int i = 0; i < 8; i++) {
            const int idx = i * 256 + tid;
            const int tsr = idx >> 9;
            const int rem = idx & 511;
            const int row = rem >> 3;
            const int ch = rem & 7;
            const __nv_bfloat16* base =
                (tsr == 0) ? Khi : (tsr == 1) ? Klo : (tsr == 2) ? Vhi : Vlo;
            const __nv_bfloat16* src = base + kg + (size_t)(n0 + row) * D + ch * 8;
            CP16(sb + 2 * AQT + stage * ASTG + tsr * AKT + row * APITCH + ch * 16, src);
        }
    };

    prefetch_kv(0, 0); CP_COMMIT();
    if (1 < ntiles) prefetch_kv(1, 1);
    CP_COMMIT();

    float oacc[8][4];
#pragma unroll
    for (int j = 0; j < 8; j++)
#pragma unroll
        for (int e = 0; e < 4; e++) oacc[j][e] = 0.f;

    float m1 = -INFINITY, m2 = -INFINITY, l1 = 0.f, l2 = 0.f;
    uint32_t qh[4][4], ql[4][4];

    const int lr = lane & 15;
    const int lh = lane >> 4;
    const int br = (lane & 7) + ((lane >> 4) & 1) * 8;
    const int bk = ((lane >> 3) & 1) * 16;
    const int vs_off = ((lane >> 3) & 1) * 8 + (lane & 7);
    const int vdb = (lane >> 4) * 16;
    const int qbw = m0 + wid * 16;

    int stage = 0;
    for (int jt = 0; jt < ntiles; jt++) {
        CP_WAIT1();
        __syncthreads();
        const uint32_t kbase = sb + 2 * AQT + stage * ASTG;
        const uint32_t vbase = kbase + 2 * AKT;

        if (jt == 0) {
#pragma unroll
            for (int ks = 0; ks < 4; ks++) {
                const uint32_t ad = sb +
                    (uint32_t)((wid * 16 + lr) * APITCH + ks * 32 + lh * 16);
                LDSM_X4(qh[ks][0], qh[ks][1], qh[ks][2], qh[ks][3], ad);
                LDSM_X4(ql[ks][0], ql[ks][1], ql[ks][2], ql[ks][3], ad + AQT);
            }
        }

        float sacc[8][4];
#pragma unroll
        for (int j = 0; j < 8; j++)
#pragma unroll
            for (int e = 0; e < 4; e++) sacc[j][e] = 0.f;

#pragma unroll
        for (int ks = 0; ks < 4; ks++) {
#pragma unroll
            for (int np = 0; np < 4; np++) {
                const uint32_t bd = kbase +
                    (uint32_t)((np * 16 + br) * APITCH + ks * 32 + bk);
                uint32_t t0, t1, t2, t3, u0, u1, u2, u3;
                LDSM_X4(t0, t1, t2, t3, bd);
                LDSM_X4(u0, u1, u2, u3, bd + AKT);
                MMA_BF16(sacc[np * 2], qh[ks], t0, t1);
                MMA_BF16(sacc[np * 2], qh[ks], u0, u1);
                MMA_BF16(sacc[np * 2], ql[ks], t0, t1);
                MMA_BF16(sacc[np * 2 + 1], qh[ks], t2, t3);
                MMA_BF16(sacc[np * 2 + 1], qh[ks], u2, u3);
                MMA_BF16(sacc[np * 2 + 1], ql[ks], t2, t3);
            }
        }

        const int n0 = jt * 64;
        if (n0 + 63 > qbw) {
            const int r1 = qbw + (lane >> 2);
            const int r2 = r1 + 8;
#pragma unroll
            for (int j = 0; j < 8; j++) {
                const int c0 = n0 + j * 8 + (lane & 3) * 2;
                if (c0 > r1) sacc[j][0] = -INFINITY;
                if (c0 + 1 > r1) sacc[j][1] = -INFINITY;
                if (c0 > r2) sacc[j][2] = -INFINITY;
                if (c0 + 1 > r2) sacc[j][3] = -INFINITY;
            }
        }

        float mt1 = -INFINITY, mt2 = -INFINITY;
#pragma unroll
        for (int j = 0; j < 8; j++) {
            mt1 = fmaxf(mt1, fmaxf(sacc[j][0], sacc[j][1]));
            mt2 = fmaxf(mt2, fmaxf(sacc[j][2], sacc[j][3]));
        }
        mt1 = fmaxf(mt1, __shfl_xor_sync(0xFFFFFFFFu, mt1, 1));
        mt1 = fmaxf(mt1, __shfl_xor_sync(0xFFFFFFFFu, mt1, 2));
        mt2 = fmaxf(mt2, __shfl_xor_sync(0xFFFFFFFFu, mt2, 1));
        mt2 = fmaxf(mt2, __shfl_xor_sync(0xFFFFFFFFu, mt2, 2));

        const float nm1 = fmaxf(m1, mt1);
        const float nm2 = fmaxf(m2, mt2);
        const float f1 = ex2f(m1 - nm1);
        const float f2 = ex2f(m2 - nm2);
        m1 = nm1; m2 = nm2;

        float rs1 = 0.f, rs2 = 0.f;
#pragma unroll
        for (int j = 0; j < 8; j++) {
            sacc[j][0] = ex2f(sacc[j][0] - nm1);
            sacc[j][1] = ex2f(sacc[j][1] - nm1);
            sacc[j][2] = ex2f(sacc[j][2] - nm2);
            sacc[j][3] = ex2f(sacc[j][3] - nm2);
            rs1 += sacc[j][0] + sacc[j][1];
            rs2 += sacc[j][2] + sacc[j][3];
        }
        rs1 += __shfl_xor_sync(0xFFFFFFFFu, rs1, 1);
        rs1 += __shfl_xor_sync(0xFFFFFFFFu, rs1, 2);
        rs2 += __shfl_xor_sync(0xFFFFFFFFu, rs2, 1);
        rs2 += __shfl_xor_sync(0xFFFFFFFFu, rs2, 2);
        l1 = l1 * f1 + rs1;
        l2 = l2 * f2 + rs2;

#pragma unroll
        for (int j = 0; j < 8; j++) {
            oacc[j][0] *= f1; oacc[j][1] *= f1;
            oacc[j][2] *= f2; oacc[j][3] *= f2;
        }

#pragma unroll
        for (int t = 0; t < 4; t++) {
            uint32_t ph[4], pl[4];
            split_pack(sacc[2 * t][0], sacc[2 * t][1], ph[0], pl[0]);
            split_pack(sacc[2 * t][2], sacc[2 * t][3], ph[1], pl[1]);
            split_pack(sacc[2 * t + 1][0], sacc[2 * t + 1][1], ph[2], pl[2]);
            split_pack(sacc[2 * t + 1][2], sacc[2 * t + 1][3], ph[3], pl[3]);
#pragma unroll
            for (int dp = 0; dp < 4; dp++) {
                const uint32_t vd = vbase +
                    (uint32_t)((t * 16 + vs_off) * APITCH + vdb + dp * 32);
                uint32_t t0, t1, t2, t3, u0, u1, u2, u3;
                LDSM_X4_T(t0, t1, t2, t3, vd);
                LDSM_X4_T(u0, u1, u2, u3, vd + AKT);
                MMA_BF16(oacc[dp * 2], ph, t0, t1);
                MMA_BF16(oacc[dp * 2], ph, u0, u1);
                MMA_BF16(oacc[dp * 2], pl, t0, t1);
                MMA_BF16(oacc[dp * 2 + 1], ph, t2, t3);
                MMA_BF16(oacc[dp * 2 + 1], ph, u2, u3);
                MMA_BF16(oacc[dp * 2 + 1], pl, t2, t3);
            }
        }

        if (jt + 2 < ntiles) {
            int ps = stage + 2; if (ps >= 3) ps -= 3;
            prefetch_kv(jt + 2, ps);
        }
        CP_COMMIT();
        if (++stage == 3) stage = 0;
    }

    const float inv1 = 1.f / l1;
    const float inv2 = 1.f / l2;
    const int r1 = m0 + wid * 16 + (lane >> 2);
    const int r2 = r1 + 8;
    const int cbase = h * DH + (lane & 3) * 2;
#pragma unroll
    for (int j = 0; j < 8; j++) {
        const int cc = cbase + j * 8;
        uint32_t hp, lp;
        split_pack(oacc[j][0] * inv1, oacc[j][1] * inv1, hp, lp);
        *reinterpret_cast<uint32_t*>(Ohi + ((size_t)b * L + r1) * D + cc) = hp;
        *reinterpret_cast<uint32_t*>(Olo + ((size_t)b * L + r1) * D + cc) = lp;
        split_pack(oacc[j][2] * inv2, oacc[j][3] * inv2, hp, lp);
        *reinterpret_cast<uint32_t*>(Ohi + ((size_t)b * L + r2) * D + cc) = hp;
        *reinterpret_cast<uint32_t*>(Olo + ((size_t)b * L + r2) * D + cc) = lp;
    }
}

// ---------------------------------------------------------------------------
// Launch
// ---------------------------------------------------------------------------
extern "C" void kernel_launch(void* const* d_in, const int* in_sizes, int n_in,
                              void* d_out, int out_size)
{
    const float* q_in = (const float*)d_in[0];
    const float* k_in = (const float*)d_in[1];
    const float* v_in = (const float*)d_in[2];
    const float* Wq   = (const float*)d_in[3];
    const float* Wk   = (const float*)d_in[4];
    const float* Wv   = (const float*)d_in[5];
    const float* Wo   = (const float*)d_in[6];
    float* out = (float*)d_out;

    __nv_bfloat16 *qh, *qlp, *kh, *kl, *vh, *vl, *oh, *ol;
    cudaGetSymbolAddress((void**)&qh, g_q_hi);
    cudaGetSymbolAddress((void**)&qlp, g_q_lo);
    cudaGetSymbolAddress((void**)&kh, g_k_hi);
    cudaGetSymbolAddress((void**)&kl, g_k_lo);
    cudaGetSymbolAddress((void**)&vh, g_v_hi);
    cudaGetSymbolAddress((void**)&vl, g_v_lo);
    cudaGetSymbolAddress((void**)&oh, g_o_hi);
    cudaGetSymbolAddress((void**)&ol, g_o_lo);

    cudaFuncSetAttribute(gemm_qkv_kernel,
                         cudaFuncAttributeMaxDynamicSharedMemorySize, GEMM_SMEM);
    cudaFuncSetAttribute(gemm_o_kernel,
                         cudaFuncAttributeMaxDynamicSharedMemorySize, GEMM_SMEM);
    cudaFuncSetAttribute(attn_mma_kernel,
                         cudaFuncAttributeMaxDynamicSharedMemorySize, ATTN_SMEM);

    const int Nrows = B * L;
    const int nInp4 = Nrows * D / 4;
    const int nW4   = D * D / 4;

    dim3 wgrid((nW4 + 255) / 256, 4);
    split_w4_kernel<<<wgrid, 256>>>(Wq, Wk, Wv, Wo);
    dim3 igrid((nInp4 + 255) / 256, 3);
    split_in3_kernel<<<igrid, 256>>>(q_in, k_in, v_in);

    // Merged Q/K/V projections (one launch, z selects operand set)
    dim3 ggrid(D / 128, Nrows / 128, 3);   // (8, 64, 3) = 1536 CTAs
    gemm_qkv_kernel<<<ggrid, 256, GEMM_SMEM>>>();

    dim3 agrid(L / 128, B * H);
    attn_mma_kernel<<<agrid, 256, ATTN_SMEM>>>(qh, qlp, kh, kl, vh, vl, oh, ol);

    dim3 ogrid(D / 128, Nrows / 128, 1);
    gemm_o_kernel<<<ogrid, 256, GEMM_SMEM>>>(out);
}

// round 16
// speedup vs baseline: 1.0397x; 1.0397x over previous
#include <cuda_runtime.h>
#include <cuda_bf16.h>
#include <math.h>
#include <stdint.h>

// Problem constants
#define B 4
#define L 2048
#define S 2048
#define D 1024
#define H 16
#define DH 64

// ---------------------------------------------------------------------------
// Scratch (device globals — no allocation allowed)
// ---------------------------------------------------------------------------
__device__ __nv_bfloat16 g_ain_hi[B * L * D];
__device__ __nv_bfloat16 g_ain_lo[B * L * D];
__device__ __nv_bfloat16 g_bin_hi[B * L * D];
__device__ __nv_bfloat16 g_bin_lo[B * L * D];
__device__ __nv_bfloat16 g_cin_hi[B * L * D];
__device__ __nv_bfloat16 g_cin_lo[B * L * D];
__device__ __nv_bfloat16 g_wq_hi[D * D];
__device__ __nv_bfloat16 g_wq_lo[D * D];
__device__ __nv_bfloat16 g_wk_hi[D * D];
__device__ __nv_bfloat16 g_wk_lo[D * D];
__device__ __nv_bfloat16 g_wv_hi[D * D];
__device__ __nv_bfloat16 g_wv_lo[D * D];
__device__ __nv_bfloat16 g_wo_hi[D * D];
__device__ __nv_bfloat16 g_wo_lo[D * D];
__device__ __nv_bfloat16 g_q_hi[B * L * D];
__device__ __nv_bfloat16 g_q_lo[B * L * D];
__device__ __nv_bfloat16 g_k_hi[B * S * D];
__device__ __nv_bfloat16 g_k_lo[B * S * D];
__device__ __nv_bfloat16 g_v_hi[B * S * D];
__device__ __nv_bfloat16 g_v_lo[B * S * D];
__device__ __nv_bfloat16 g_o_hi[B * L * D];
__device__ __nv_bfloat16 g_o_lo[B * L * D];

// ---------------------------------------------------------------------------
// Helpers (baseline compute_103-safe PTX only)
// ---------------------------------------------------------------------------
__device__ __forceinline__ uint32_t smem_u32(const void* p) {
    uint32_t a;
    asm("{ .reg .u64 t; cvta.to.shared.u64 t, %1; cvt.u32.u64 %0, t; }"
        : "=r"(a) : "l"(p));
    return a;
}

#define CP16(dst, src) \
    asm volatile("cp.async.cg.shared.global [%0], [%1], 16;" \
        :: "r"(dst), "l"(src) : "memory")

#define CP_COMMIT() asm volatile("cp.async.commit_group;" ::: "memory")
#define CP_WAIT1()  asm volatile("cp.async.wait_group 1;" ::: "memory")

#define LDSM_X4(r0, r1, r2, r3, addr) \
    asm volatile("ldmatrix.sync.aligned.m8n8.x4.shared.b16 {%0,%1,%2,%3}, [%4];" \
        : "=r"(r0), "=r"(r1), "=r"(r2), "=r"(r3) : "r"(addr))

#define LDSM_X4_T(r0, r1, r2, r3, addr) \
    asm volatile("ldmatrix.sync.aligned.m8n8.x4.trans.shared.b16 {%0,%1,%2,%3}, [%4];" \
        : "=r"(r0), "=r"(r1), "=r"(r2), "=r"(r3) : "r"(addr))

#define MMA_BF16(c, a, b0, b1) \
    asm volatile("mma.sync.aligned.m16n8k16.row.col.f32.bf16.bf16.f32 " \
        "{%0,%1,%2,%3}, {%4,%5,%6,%7}, {%8,%9}, {%0,%1,%2,%3};" \
        : "+f"((c)[0]), "+f"((c)[1]), "+f"((c)[2]), "+f"((c)[3]) \
        : "r"((a)[0]), "r"((a)[1]), "r"((a)[2]), "r"((a)[3]), \
          "r"(b0), "r"(b1))

__device__ __forceinline__ float ex2f(float x) {
    float r;
    asm("ex2.approx.f32 %0, %1;" : "=f"(r) : "f"(x));
    return r;
}

__device__ __forceinline__ uint32_t pack_bf16x2(float lo, float hi) {
    uint32_t r;
    asm("cvt.rn.bf16x2.f32 %0, %1, %2;" : "=r"(r) : "f"(hi), "f"(lo));
    return r;
}

__device__ __forceinline__ void split_pack(float v0, float v1,
                                           uint32_t& hp, uint32_t& lp) {
    __nv_bfloat16 h0 = __float2bfloat16(v0);
    __nv_bfloat16 h1 = __float2bfloat16(v1);
    __nv_bfloat162 hh(h0, h1);
    hp = *reinterpret_cast<uint32_t*>(&hh);
    lp = pack_bf16x2(v0 - __bfloat162float(h0), v1 - __bfloat162float(h1));
}

// ---------------------------------------------------------------------------
// Split kernels (merged: weights x4, inputs x3)
// ---------------------------------------------------------------------------
__device__ __forceinline__ void split_body(const float* __restrict__ x,
                                           __nv_bfloat16* __restrict__ hi,
                                           __nv_bfloat16* __restrict__ lo, int n4)
{
    int i = blockIdx.x * blockDim.x + threadIdx.x;
    if (i >= n4) return;
    float4 v = reinterpret_cast<const float4*>(x)[i];
    uint2 hv, lv;
    split_pack(v.x, v.y, hv.x, lv.x);
    split_pack(v.z, v.w, hv.y, lv.y);
    reinterpret_cast<uint2*>(hi)[i] = hv;
    reinterpret_cast<uint2*>(lo)[i] = lv;
}

__global__ __launch_bounds__(256)
void split_w4_kernel(const float* __restrict__ Wq, const float* __restrict__ Wk,
                     const float* __restrict__ Wv, const float* __restrict__ Wo)
{
    const int seg = blockIdx.y;
    const float* src = (seg == 0) ? Wq : (seg == 1) ? Wk : (seg == 2) ? Wv : Wo;
    __nv_bfloat16* hi = (seg == 0) ? g_wq_hi : (seg == 1) ? g_wk_hi
                       : (seg == 2) ? g_wv_hi : g_wo_hi;
    __nv_bfloat16* lo = (seg == 0) ? g_wq_lo : (seg == 1) ? g_wk_lo
                       : (seg == 2) ? g_wv_lo : g_wo_lo;
    split_body(src, hi, lo, D * D / 4);
}

__global__ __launch_bounds__(256)
void split_in3_kernel(const float* __restrict__ q, const float* __restrict__ k,
                      const float* __restrict__ v)
{
    const int seg = blockIdx.y;
    const float* src = (seg == 0) ? q : (seg == 1) ? k : v;
    __nv_bfloat16* hi = (seg == 0) ? g_ain_hi : (seg == 1) ? g_bin_hi : g_cin_hi;
    __nv_bfloat16* lo = (seg == 0) ? g_ain_lo : (seg == 1) ? g_bin_lo : g_cin_lo;
    split_body(src, hi, lo, B * L * D / 4);
}

// ---------------------------------------------------------------------------
// HMMA split-bf16 GEMM body:  Y[m, n] = sum_k A[m,k] * W[n,k]
// CTA tile 128x256, warp tile 64x64 (8 warps as 2x4), k-chunk 32.
// 3-stage cp.async ring, prefetch distance 2, one barrier per iteration.
// MMA emission is TERM-MAJOR per np-pair: same-accumulator gap = 16 MMAs,
// eliminating HMMA dependency-chain stalls (tensor pipe was 55% active).
// ---------------------------------------------------------------------------
#define KDIM 1024
#define NCH 32
#define PITCH 80
#define ATSZ (128 * PITCH)          // 10240
#define BTSZ (256 * PITCH)          // 20480
#define STAGE_B (2 * ATSZ + 2 * BTSZ)   // 61440
#define GEMM_SMEM (3 * STAGE_B)     // 184320

#define QSCALE (0.125f * 1.4426950408889634f)

template<bool BF16OUT>
__device__ __forceinline__ void gemm_body(
    const __nv_bfloat16* __restrict__ Ahi, const __nv_bfloat16* __restrict__ Alo,
    const __nv_bfloat16* __restrict__ Whi, const __nv_bfloat16* __restrict__ Wlo,
    float* __restrict__ Yf, __nv_bfloat16* __restrict__ Yhi,
    __nv_bfloat16* __restrict__ Ylo, float scale)
{
    extern __shared__ char smem[];
    const uint32_t sb = smem_u32(smem);
    const int tid = threadIdx.x;
    const int lane = tid & 31;
    const int wid = tid >> 5;
    const int warp_m = wid >> 2;      // 0..1 (64-row slab)
    const int warp_n = wid & 3;       // 0..3 (64-col slab)
    const int m0 = blockIdx.y * 128;
    const int n0 = blockIdx.x * 256;

    float acc[4][8][4];
#pragma unroll
    for (int a = 0; a < 4; a++)
#pragma unroll
        for (int b = 0; b < 8; b++)
#pragma unroll
            for (int c = 0; c < 4; c++) acc[a][b][c] = 0.f;

    auto prefetch = [&](int c, int stage) {
        const uint32_t sbase = sb + stage * STAGE_B;
        const int k0 = c * 32;
#pragma unroll
        for (int j = 0; j < 12; j++) {
            const int idx = j * 256 + tid;
            if (idx < 1024) {
                const int half = idx >> 9;            // 0 hi, 1 lo
                const int rem = idx & 511;
                const int r = rem >> 2, ch = rem & 3;
                const __nv_bfloat16* src = (half ? Alo : Ahi)
                    + (size_t)(m0 + r) * KDIM + k0 + ch * 8;
                CP16(sbase + half * ATSZ + r * PITCH + ch * 16, src);
            } else {
                const int bidx = idx - 1024;
                const int half = bidx >> 10;          // 0 hi, 1 lo
                const int rem = bidx & 1023;
                const int r = rem >> 2, ch = rem & 3;
                const __nv_bfloat16* src = (half ? Wlo : Whi)
                    + (size_t)(n0 + r) * KDIM + k0 + ch * 8;
                CP16(sbase + 2 * ATSZ + half * BTSZ + r * PITCH + ch * 16, src);
            }
        }
    };

    prefetch(0, 0); CP_COMMIT();
    prefetch(1, 1); CP_COMMIT();

    const int lr = lane & 15;
    const int lh = lane >> 4;
    const int br = (lane & 7) + ((lane >> 4) & 1) * 8;
    const int bk = ((lane >> 3) & 1) * 16;

    int stage = 0;
    for (int c = 0; c < NCH; c++) {
        CP_WAIT1();
        __syncthreads();
        const uint32_t sbase = sb + stage * STAGE_B;
        const uint32_t bbase = sbase + 2 * ATSZ;

#pragma unroll
        for (int s = 0; s < 2; s++) {
            uint32_t ah[4][4], al[4][4];
#pragma unroll
            for (int mt = 0; mt < 4; mt++) {
                const uint32_t ad = sbase +
                    (uint32_t)((warp_m * 64 + mt * 16 + lr) * PITCH + s * 32 + lh * 16);
                LDSM_X4(ah[mt][0], ah[mt][1], ah[mt][2], ah[mt][3], ad);
                LDSM_X4(al[mt][0], al[mt][1], al[mt][2], al[mt][3], ad + ATSZ);
            }
            // process n in pairs of 16-col groups (4 n8-tiles at a time)
#pragma unroll
            for (int npp = 0; npp < 2; npp++) {
                uint32_t bh[4][2], bl[4][2];
#pragma unroll
                for (int npi = 0; npi < 2; npi++) {
                    const int np = npp * 2 + npi;
                    const uint32_t bd = bbase +
                        (uint32_t)((warp_n * 64 + np * 16 + br) * PITCH + s * 32 + bk);
                    uint32_t t0, t1, t2, t3;
                    LDSM_X4(t0, t1, t2, t3, bd);
                    bh[npi * 2][0] = t0; bh[npi * 2][1] = t1;
                    bh[npi * 2 + 1][0] = t2; bh[npi * 2 + 1][1] = t3;
                    LDSM_X4(t0, t1, t2, t3, bd + BTSZ);
                    bl[npi * 2][0] = t0; bl[npi * 2][1] = t1;
                    bl[npi * 2 + 1][0] = t2; bl[npi * 2 + 1][1] = t3;
                }
                // TERM-MAJOR: same-acc gap = 16 MMAs (>= HMMA latency)
#pragma unroll
                for (int mt = 0; mt < 4; mt++)
#pragma unroll
                    for (int lj = 0; lj < 4; lj++)
                        MMA_BF16(acc[mt][npp * 4 + lj], ah[mt], bh[lj][0], bh[lj][1]);
#pragma unroll
                for (int mt = 0; mt < 4; mt++)
#pragma unroll
                    for (int lj = 0; lj < 4; lj++)
                        MMA_BF16(acc[mt][npp * 4 + lj], ah[mt], bl[lj][0], bl[lj][1]);
#pragma unroll
                for (int mt = 0; mt < 4; mt++)
#pragma unroll
                    for (int lj = 0; lj < 4; lj++)
                        MMA_BF16(acc[mt][npp * 4 + lj], al[mt], bh[lj][0], bh[lj][1]);
            }
        }
        if (c + 2 < NCH) {
            int ps = stage + 2; if (ps >= 3) ps -= 3;
            prefetch(c + 2, ps);
        }
        CP_COMMIT();
        if (++stage == 3) stage = 0;
    }

    const int gr = lane >> 2;
    const int gc = (lane & 3) * 2;
    const int row0 = m0 + warp_m * 64;
    const int col0 = n0 + warp_n * 64;
#pragma unroll
    for (int mt = 0; mt < 4; mt++) {
#pragma unroll
        for (int nt = 0; nt < 8; nt++) {
            const int r0 = row0 + mt * 16 + gr;
            const int cc = col0 + nt * 8 + gc;
            if (BF16OUT) {
                uint32_t hp, lp;
                split_pack(acc[mt][nt][0] * scale, acc[mt][nt][1] * scale, hp, lp);
                *reinterpret_cast<uint32_t*>(Yhi + (size_t)r0 * KDIM + cc) = hp;
                *reinterpret_cast<uint32_t*>(Ylo + (size_t)r0 * KDIM + cc) = lp;
                split_pack(acc[mt][nt][2] * scale, acc[mt][nt][3] * scale, hp, lp);
                *reinterpret_cast<uint32_t*>(Yhi + (size_t)(r0 + 8) * KDIM + cc) = hp;
                *reinterpret_cast<uint32_t*>(Ylo + (size_t)(r0 + 8) * KDIM + cc) = lp;
            } else {
                float* p0 = Yf + (size_t)r0 * KDIM + cc;
                float* p1 = p0 + 8 * KDIM;
                asm volatile("st.global.v2.f32 [%0], {%1, %2};"
                    :: "l"(p0), "f"(acc[mt][nt][0]), "f"(acc[mt][nt][1]) : "memory");
                asm volatile("st.global.v2.f32 [%0], {%1, %2};"
                    :: "l"(p1), "f"(acc[mt][nt][2]), "f"(acc[mt][nt][3]) : "memory");
            }
        }
    }
}

// Merged Q/K/V projections: blockIdx.z selects operand set (all device symbols).
__global__ __launch_bounds__(256, 1)
void gemm_qkv_kernel()
{
    const int z = blockIdx.z;
    const __nv_bfloat16* Ahi = (z == 0) ? g_ain_hi : (z == 1) ? g_bin_hi : g_cin_hi;
    const __nv_bfloat16* Alo = (z == 0) ? g_ain_lo : (z == 1) ? g_bin_lo : g_cin_lo;
    const __nv_bfloat16* Whi = (z == 0) ? g_wq_hi : (z == 1) ? g_wk_hi : g_wv_hi;
    const __nv_bfloat16* Wlo = (z == 0) ? g_wq_lo : (z == 1) ? g_wk_lo : g_wv_lo;
    __nv_bfloat16* Yhi = (z == 0) ? g_q_hi : (z == 1) ? g_k_hi : g_v_hi;
    __nv_bfloat16* Ylo = (z == 0) ? g_q_lo : (z == 1) ? g_k_lo : g_v_lo;
    const float sc = (z == 0) ? QSCALE : 1.f;
    gemm_body<true>(Ahi, Alo, Whi, Wlo, nullptr, Yhi, Ylo, sc);
}

// Output projection: fp32 result into harness buffer.
__global__ __launch_bounds__(256, 1)
void gemm_o_kernel(float* __restrict__ out)
{
    gemm_body<false>(g_o_hi, g_o_lo, g_wo_hi, g_wo_lo, out, nullptr, nullptr, 1.f);
}

// ---------------------------------------------------------------------------
// HMMA flash attention (causal), split-bf16, log2-domain softmax.
// CTA: 128 q-rows (8 warps x 16), kv-tiles of 64, dh=64.
// 3-stage kv ring; QK^T and PV MMAs emitted term-major (gap 8).
// ---------------------------------------------------------------------------
#define APITCH 144
#define AQT (128 * APITCH)
#define AKT (64 * APITCH)
#define ASTG (4 * AKT)
#define ATTN_SMEM (2 * AQT + 3 * ASTG)   // 147456

__global__ __launch_bounds__(256, 1)
void attn_mma_kernel(const __nv_bfloat16* __restrict__ Qhi,
                     const __nv_bfloat16* __restrict__ Qlo,
                     const __nv_bfloat16* __restrict__ Khi,
                     const __nv_bfloat16* __restrict__ Klo,
                     const __nv_bfloat16* __restrict__ Vhi,
                     const __nv_bfloat16* __restrict__ Vlo,
                     __nv_bfloat16* __restrict__ Ohi,
                     __nv_bfloat16* __restrict__ Olo)
{
    extern __shared__ char smem[];
    const uint32_t sb = smem_u32(smem);
    const int tid = threadIdx.x;
    const int lane = tid & 31;
    const int wid = tid >> 5;
    const int mq = (L / 128 - 1) - blockIdx.x;
    const int bh = blockIdx.y;
    const int b = bh >> 4;
    const int h = bh & 15;
    const int m0 = mq * 128;
    const int ntiles = mq * 2 + 2;

    const size_t qg = ((size_t)b * L + m0) * D + h * DH;
    const size_t kg = (size_t)b * S * D + h * DH;

#pragma unroll
    for (int i = 0; i < 8; i++) {
        const int idx = i * 256 + tid;
        const int tsr = idx >> 10;
        const int rem = idx & 1023;
        const int row = rem >> 3;
        const int ch = rem & 7;
        const __nv_bfloat16* src = (tsr ? Qlo : Qhi) + qg + (size_t)row * D + ch * 8;
        CP16(sb + tsr * AQT + row * APITCH + ch * 16, src);
    }

    auto prefetch_kv = [&](int j, int stage) {
        const int n0 = j * 64;
#pragma unroll
        for (int i = 0; i < 8; i++) {
            const int idx = i * 256 + tid;
            const int tsr = idx >> 9;
            const int rem = idx & 511;
            const int row = rem >> 3;
            const int ch = rem & 7;
            const __nv_bfloat16* base =
                (tsr == 0) ? Khi : (tsr == 1) ? Klo : (tsr == 2) ? Vhi : Vlo;
            const __nv_bfloat16* src = base + kg + (size_t)(n0 + row) * D + ch * 8;
            CP16(sb + 2 * AQT + stage * ASTG + tsr * AKT + row * APITCH + ch * 16, src);
        }
    };

    prefetch_kv(0, 0); CP_COMMIT();
    if (1 < ntiles) prefetch_kv(1, 1);
    CP_COMMIT();

    float oacc[8][4];
#pragma unroll
    for (int j = 0; j < 8; j++)
#pragma unroll
        for (int e = 0; e < 4; e++) oacc[j][e] = 0.f;

    float m1 = -INFINITY, m2 = -INFINITY, l1 = 0.f, l2 = 0.f;
    uint32_t qh[4][4], ql[4][4];

    const int lr = lane & 15;
    const int lh = lane >> 4;
    const int br = (lane & 7) + ((lane >> 4) & 1) * 8;
    const int bk = ((lane >> 3) & 1) * 16;
    const int vs_off = ((lane >> 3) & 1) * 8 + (lane & 7);
    const int vdb = (lane >> 4) * 16;
    const int qbw = m0 + wid * 16;

    int stage = 0;
    for (int jt = 0; jt < ntiles; jt++) {
        CP_WAIT1();
        __syncthreads();
        const uint32_t kbase = sb + 2 * AQT + stage * ASTG;
        const uint32_t vbase = kbase + 2 * AKT;

        if (jt == 0) {
#pragma unroll
            for (int ks = 0; ks < 4; ks++) {
                const uint32_t ad = sb +
                    (uint32_t)((wid * 16 + lr) * APITCH + ks * 32 + lh * 16);
                LDSM_X4(qh[ks][0], qh[ks][1], qh[ks][2], qh[ks][3], ad);
                LDSM_X4(ql[ks][0], ql[ks][1], ql[ks][2], ql[ks][3], ad + AQT);
            }
        }

        // ---- S = Q K^T (term-major per ks; same-acc gap = 8 MMAs) ----
        float sacc[8][4];
#pragma unroll
        for (int j = 0; j < 8; j++)
#pragma unroll
            for (int e = 0; e < 4; e++) sacc[j][e] = 0.f;

#pragma unroll
        for (int ks = 0; ks < 4; ks++) {
            uint32_t kfh[8][2], kfl[8][2];
#pragma unroll
            for (int np = 0; np < 4; np++) {
                const uint32_t bd = kbase +
                    (uint32_t)((np * 16 + br) * APITCH + ks * 32 + bk);
                uint32_t t0, t1, t2, t3;
                LDSM_X4(t0, t1, t2, t3, bd);
                kfh[np * 2][0] = t0; kfh[np * 2][1] = t1;
                kfh[np * 2 + 1][0] = t2; kfh[np * 2 + 1][1] = t3;
                LDSM_X4(t0, t1, t2, t3, bd + AKT);
                kfl[np * 2][0] = t0; kfl[np * 2][1] = t1;
                kfl[np * 2 + 1][0] = t2; kfl[np * 2 + 1][1] = t3;
            }
#pragma unroll
            for (int nj = 0; nj < 8; nj++)
                MMA_BF16(sacc[nj], qh[ks], kfh[nj][0], kfh[nj][1]);
#pragma unroll
            for (int nj = 0; nj < 8; nj++)
                MMA_BF16(sacc[nj], qh[ks], kfl[nj][0], kfl[nj][1]);
#pragma unroll
            for (int nj = 0; nj < 8; nj++)
                MMA_BF16(sacc[nj], ql[ks], kfh[nj][0], kfh[nj][1]);
        }

        const int n0 = jt * 64;
        if (n0 + 63 > qbw) {
            const int r1 = qbw + (lane >> 2);
            const int r2 = r1 + 8;
#pragma unroll
            for (int j = 0; j < 8; j++) {
                const int c0 = n0 + j * 8 + (lane & 3) * 2;
                if (c0 > r1) sacc[j][0] = -INFINITY;
                if (c0 + 1 > r1) sacc[j][1] = -INFINITY;
                if (c0 > r2) sacc[j][2] = -INFINITY;
                if (c0 + 1 > r2) sacc[j][3] = -INFINITY;
            }
        }

        float mt1 = -INFINITY, mt2 = -INFINITY;
#pragma unroll
        for (int j = 0; j < 8; j++) {
            mt1 = fmaxf(mt1, fmaxf(sacc[j][0], sacc[j][1]));
            mt2 = fmaxf(mt2, fmaxf(sacc[j][2], sacc[j][3]));
        }
        mt1 = fmaxf(mt1, __shfl_xor_sync(0xFFFFFFFFu, mt1, 1));
        mt1 = fmaxf(mt1, __shfl_xor_sync(0xFFFFFFFFu, mt1, 2));
        mt2 = fmaxf(mt2, __shfl_xor_sync(0xFFFFFFFFu, mt2, 1));
        mt2 = fmaxf(mt2, __shfl_xor_sync(0xFFFFFFFFu, mt2, 2));

        const float nm1 = fmaxf(m1, mt1);
        const float nm2 = fmaxf(m2, mt2);
        const float f1 = ex2f(m1 - nm1);
        const float f2 = ex2f(m2 - nm2);
        m1 = nm1; m2 = nm2;

        float rs1 = 0.f, rs2 = 0.f;
#pragma unroll
        for (int j = 0; j < 8; j++) {
            sacc[j][0] = ex2f(sacc[j][0] - nm1);
            sacc[j][1] = ex2f(sacc[j][1] - nm1);
            sacc[j][2] = ex2f(sacc[j][2] - nm2);
            sacc[j][3] = ex2f(sacc[j][3] - nm2);
            rs1 += sacc[j][0] + sacc[j][1];
            rs2 += sacc[j][2] + sacc[j][3];
        }
        rs1 += __shfl_xor_sync(0xFFFFFFFFu, rs1, 1);
        rs1 += __shfl_xor_sync(0xFFFFFFFFu, rs1, 2);
        rs2 += __shfl_xor_sync(0xFFFFFFFFu, rs2, 1);
        rs2 += __shfl_xor_sync(0xFFFFFFFFu, rs2, 2);
        l1 = l1 * f1 + rs1;
        l2 = l2 * f2 + rs2;

#pragma unroll
        for (int j = 0; j < 8; j++) {
            oacc[j][0] *= f1; oacc[j][1] *= f1;
            oacc[j][2] *= f2; oacc[j][3] *= f2;
        }

        // ---- O += P V (term-major per t; same-acc gap = 8 MMAs) ----
#pragma unroll
        for (int t = 0; t < 4; t++) {
            uint32_t ph[4], pl[4];
            split_pack(sacc[2 * t][0], sacc[2 * t][1], ph[0], pl[0]);
            split_pack(sacc[2 * t][2], sacc[2 * t][3], ph[1], pl[1]);
            split_pack(sacc[2 * t + 1][0], sacc[2 * t + 1][1], ph[2], pl[2]);
            split_pack(sacc[2 * t + 1][2], sacc[2 * t + 1][3], ph[3], pl[3]);
            uint32_t vfh[8][2], vfl[8][2];
#pragma unroll
            for (int dp = 0; dp < 4; dp++) {
                const uint32_t vd = vbase +
                    (uint32_t)((t * 16 + vs_off) * APITCH + vdb + dp * 32);
                uint32_t t0, t1, t2, t3;
                LDSM_X4_T(t0, t1, t2, t3, vd);
                vfh[dp * 2][0] = t0; vfh[dp * 2][1] = t1;
                vfh[dp * 2 + 1][0] = t2; vfh[dp * 2 + 1][1] = t3;
                LDSM_X4_T(t0, t1, t2, t3, vd + AKT);
                vfl[dp * 2][0] = t0; vfl[dp * 2][1] = t1;
                vfl[dp * 2 + 1][0] = t2; vfl[dp * 2 + 1][1] = t3;
            }
#pragma unroll
            for (int nj = 0; nj < 8; nj++)
                MMA_BF16(oacc[nj], ph, vfh[nj][0], vfh[nj][1]);
#pragma unroll
            for (int nj = 0; nj < 8; nj++)
                MMA_BF16(oacc[nj], ph, vfl[nj][0], vfl[nj][1]);
#pragma unroll
            for (int nj = 0; nj < 8; nj++)
                MMA_BF16(oacc[nj], pl, vfh[nj][0], vfh[nj][1]);
        }

        if (jt + 2 < ntiles) {
            int ps = stage + 2; if (ps >= 3) ps -= 3;
            prefetch_kv(jt + 2, ps);
        }
        CP_COMMIT();
        if (++stage == 3) stage = 0;
    }

    const float inv1 = 1.f / l1;
    const float inv2 = 1.f / l2;
    const int r1 = m0 + wid * 16 + (lane >> 2);
    const int r2 = r1 + 8;
    const int cbase = h * DH + (lane & 3) * 2;
#pragma unroll
    for (int j = 0; j < 8; j++) {
        const int cc = cbase + j * 8;
        uint32_t hp, lp;
        split_pack(oacc[j][0] * inv1, oacc[j][1] * inv1, hp, lp);
        *reinterpret_cast<uint32_t*>(Ohi + ((size_t)b * L + r1) * D + cc) = hp;
        *reinterpret_cast<uint32_t*>(Olo + ((size_t)b * L + r1) * D + cc) = lp;
        split_pack(oacc[j][2] * inv2, oacc[j][3] * inv2, hp, lp);
        *reinterpret_cast<uint32_t*>(Ohi + ((size_t)b * L + r2) * D + cc) = hp;
        *reinterpret_cast<uint32_t*>(Olo + ((size_t)b * L + r2) * D + cc) = lp;
    }
}

// ---------------------------------------------------------------------------
// Launch
// ---------------------------------------------------------------------------
extern "C" void kernel_launch(void* const* d_in, const int* in_sizes, int n_in,
                              void* d_out, int out_size)
{
    const float* q_in = (const float*)d_in[0];
    const float* k_in = (const float*)d_in[1];
    const float* v_in = (const float*)d_in[2];
    const float* Wq   = (const float*)d_in[3];
    const float* Wk   = (const float*)d_in[4];
    const float* Wv   = (const float*)d_in[5];
    const float* Wo   = (const float*)d_in[6];
    float* out = (float*)d_out;

    __nv_bfloat16 *qh, *qlp, *kh, *kl, *vh, *vl, *oh, *ol;
    cudaGetSymbolAddress((void**)&qh, g_q_hi);
    cudaGetSymbolAddress((void**)&qlp, g_q_lo);
    cudaGetSymbolAddress((void**)&kh, g_k_hi);
    cudaGetSymbolAddress((void**)&kl, g_k_lo);
    cudaGetSymbolAddress((void**)&vh, g_v_hi);
    cudaGetSymbolAddress((void**)&vl, g_v_lo);
    cudaGetSymbolAddress((void**)&oh, g_o_hi);
    cudaGetSymbolAddress((void**)&ol, g_o_lo);

    cudaFuncSetAttribute(gemm_qkv_kernel,
                         cudaFuncAttributeMaxDynamicSharedMemorySize, GEMM_SMEM);
    cudaFuncSetAttribute(gemm_o_kernel,
                         cudaFuncAttributeMaxDynamicSharedMemorySize, GEMM_SMEM);
    cudaFuncSetAttribute(attn_mma_kernel,
                         cudaFuncAttributeMaxDynamicSharedMemorySize, ATTN_SMEM);

    const int Nrows = B * L;
    const int nInp4 = Nrows * D / 4;
    const int nW4   = D * D / 4;

    dim3 wgrid((nW4 + 255) / 256, 4);
    split_w4_kernel<<<wgrid, 256>>>(Wq, Wk, Wv, Wo);
    dim3 igrid((nInp4 + 255) / 256, 3);
    split_in3_kernel<<<igrid, 256>>>(q_in, k_in, v_in);

    // Merged Q/K/V projections (one launch, z selects operand set)
    dim3 ggrid(D / 256, Nrows / 128, 3);   // (4, 64, 3) = 768 CTAs
    gemm_qkv_kernel<<<ggrid, 256, GEMM_SMEM>>>();

    dim3 agrid(L / 128, B * H);
    attn_mma_kernel<<<agrid, 256, ATTN_SMEM>>>(qh, qlp, kh, kl, vh, vl, oh, ol);

    dim3 ogrid(D / 256, Nrows / 128, 1);
    gemm_o_kernel<<<ogrid, 256, GEMM_SMEM>>>(out);
}